// round 3
// baseline (speedup 1.0000x reference)
#include <cuda_runtime.h>
#include <cstdint>

#define DIMN 384
#define KS_TOT 48          // 384 / 8 k-steps
#define MAXBATCH 1024
#define BM 64
#define BN 64
#define PSTRIDE 196        // uint2 per panel row (48*4=192 + 4 pad) -> conflict-free
#define PANEL_U2 (64 * PSTRIDE)
#define SMEM_BYTES (2 * PANEL_U2 * 8)

// Scratch (no cudaMalloc allowed)
__device__ float g_Pt[DIMN * DIMN];     // transposed prod_k(1-W_k):  Pt[j][i] = P[i][j]
__device__ float g_cbar[DIMN];          // sum_i r[i] * C[i,j]
__device__ float g_t[MAXBATCH * DIMN];  // pooled intermediate

__device__ __forceinline__ uint32_t f2tf32(float x) {
    uint32_t y;
    asm("cvt.rna.tf32.f32 %0, %1;" : "=r"(y) : "f"(x));
    return y;
}

__device__ __forceinline__ void mma8(float* d, const uint32_t* a, const uint32_t* b) {
    asm volatile(
        "mma.sync.aligned.m16n8k8.row.col.f32.tf32.tf32.f32 "
        "{%0,%1,%2,%3}, {%4,%5,%6,%7}, {%8,%9}, {%0,%1,%2,%3};"
        : "+f"(d[0]), "+f"(d[1]), "+f"(d[2]), "+f"(d[3])
        : "r"(a[0]), "r"(a[1]), "r"(a[2]), "r"(a[3]),
          "r"(b[0]), "r"(b[1]));
}

// ---------------------------------------------------------------------------
// zero g_cbar
// ---------------------------------------------------------------------------
__global__ void zero_kernel() {
    g_cbar[threadIdx.x] = 0.f;
}

// ---------------------------------------------------------------------------
// prep: Pt[j][i] = prod_k(1-W_k)[i][j];  cbar[j] += r[i]*C[i][j] via RED.
// ---------------------------------------------------------------------------
__global__ void prep_kernel(const float* __restrict__ W,
                            const float* __restrict__ Bb,
                            const float* __restrict__ rw,
                            int nblocks) {
    int idx = blockIdx.x * blockDim.x + threadIdx.x;
    if (idx >= DIMN * DIMN) return;
    float p = 1.0f, c = 0.0f;
    for (int k = 0; k < nblocks; k++) {
        float om = 1.0f - W[k * DIMN * DIMN + idx];
        float b  = Bb[k * DIMN * DIMN + idx];
        p *= om;
        c = c * om + b;
    }
    int i = idx / DIMN, j = idx - i * DIMN;
    g_Pt[j * DIMN + i] = p;
    atomicAdd(&g_cbar[j], rw[i] * c);   // no return use -> RED
}

// ---------------------------------------------------------------------------
// Full-K-panel tf32 GEMM. 64x64 tile / CTA, 4 warps (32x32 warp tiles).
// Panels stored as uint2 pairs {k=8ks+t4, k=8ks+t4+4} -> LDS.64 frag loads.
// MODE 0: t   = v2 .* ((rw.*v1) @ P)   - cbar   (Asrc=v1,  Bsrc=g_Pt [n][k])
// MODE 1: out = (g_t @ linW^T)         + linb   (Asrc=g_t, Bsrc=linW [n][k])
// ---------------------------------------------------------------------------
template <int MODE>
__global__ __launch_bounds__(128)
void mma_gemm(const float* __restrict__ Asrc,
              const float* __restrict__ Bsrc,
              const float* __restrict__ rw,
              const float* __restrict__ v2,
              const float* __restrict__ addv,
              float* __restrict__ Out) {
    extern __shared__ __align__(16) uint2 sm[];
    uint2* Ap = sm;
    uint2* Bp = sm + PANEL_U2;

    const int tid  = threadIdx.x;
    const int lane = tid & 31;
    const int wid  = tid >> 5;
    const int g    = lane >> 2;
    const int t4   = lane & 3;
    const int wm   = wid & 1;
    const int wn   = wid >> 1;
    const int m0   = blockIdx.y * BM;
    const int n0   = blockIdx.x * BN;

    // ---- load A panel: 64 rows x 48 ks, task-parallel, huge MLP ----
#pragma unroll 4
    for (int task = tid; task < 64 * KS_TOT; task += 128) {
        int m = task / KS_TOT, ks = task - m * KS_TOT;
        const float* src = &Asrc[(m0 + m) * DIMN + ks * 8];
        float4 lo = *(const float4*)src;
        float4 hi = *(const float4*)(src + 4);
        if (MODE == 0) {
            float4 wl = *(const float4*)&rw[ks * 8];
            float4 wh = *(const float4*)&rw[ks * 8 + 4];
            lo.x *= wl.x; lo.y *= wl.y; lo.z *= wl.z; lo.w *= wl.w;
            hi.x *= wh.x; hi.y *= wh.y; hi.z *= wh.z; hi.w *= wh.w;
        }
        uint4* dst = (uint4*)&Ap[m * PSTRIDE + ks * 4];
        dst[0] = make_uint4(f2tf32(lo.x), f2tf32(hi.x), f2tf32(lo.y), f2tf32(hi.y));
        dst[1] = make_uint4(f2tf32(lo.z), f2tf32(hi.z), f2tf32(lo.w), f2tf32(hi.w));
    }
    // ---- load B panel: Bsrc is [n][k] row-major for both modes ----
#pragma unroll 4
    for (int task = tid; task < 64 * KS_TOT; task += 128) {
        int n = task / KS_TOT, ks = task - n * KS_TOT;
        const float* src = &Bsrc[(n0 + n) * DIMN + ks * 8];
        float4 lo = *(const float4*)src;
        float4 hi = *(const float4*)(src + 4);
        uint4* dst = (uint4*)&Bp[n * PSTRIDE + ks * 4];
        dst[0] = make_uint4(f2tf32(lo.x), f2tf32(hi.x), f2tf32(lo.y), f2tf32(hi.y));
        dst[1] = make_uint4(f2tf32(lo.z), f2tf32(hi.z), f2tf32(lo.w), f2tf32(hi.w));
    }
    __syncthreads();

    // ---- compute: 48 ks-steps, 8 MMAs each, no barriers ----
    float acc[2][4][4];
#pragma unroll
    for (int mi = 0; mi < 2; mi++)
#pragma unroll
        for (int nf = 0; nf < 4; nf++)
#pragma unroll
            for (int c = 0; c < 4; c++) acc[mi][nf][c] = 0.f;

    const uint2* a0 = &Ap[(wm * 32 + g) * PSTRIDE];       // +16*PSTRIDE for mi=1
    const uint2* b0 = &Bp[(wn * 32 + g) * PSTRIDE];       // +8*PSTRIDE per nf

#pragma unroll 4
    for (int ks = 0; ks < KS_TOT; ks++) {
        const int off = ks * 4 + t4;
        uint32_t a[2][4];
#pragma unroll
        for (int mi = 0; mi < 2; mi++) {
            uint2 lo = a0[mi * 16 * PSTRIDE + off];
            uint2 hi = a0[(mi * 16 + 8) * PSTRIDE + off];
            a[mi][0] = lo.x; a[mi][1] = hi.x; a[mi][2] = lo.y; a[mi][3] = hi.y;
        }
        uint32_t b[4][2];
#pragma unroll
        for (int nf = 0; nf < 4; nf++) {
            uint2 u = b0[nf * 8 * PSTRIDE + off];
            b[nf][0] = u.x; b[nf][1] = u.y;
        }
#pragma unroll
        for (int mi = 0; mi < 2; mi++)
#pragma unroll
            for (int nf = 0; nf < 4; nf++)
                mma8(acc[mi][nf], a[mi], b[nf]);
    }

    // ---- epilogue ----
#pragma unroll
    for (int mi = 0; mi < 2; mi++) {
        const int r0 = m0 + wm * 32 + mi * 16 + g;
#pragma unroll
        for (int nf = 0; nf < 4; nf++) {
            const int col = n0 + wn * 32 + nf * 8 + 2 * t4;
            float2 ad = *(const float2*)&addv[col];
            float* acp = acc[mi][nf];
            if (MODE == 0) {
                float2 va = *(const float2*)&v2[r0 * DIMN + col];
                float2 vb = *(const float2*)&v2[(r0 + 8) * DIMN + col];
                *(float2*)&Out[r0 * DIMN + col] =
                    make_float2(va.x * acp[0] - ad.x, va.y * acp[1] - ad.y);
                *(float2*)&Out[(r0 + 8) * DIMN + col] =
                    make_float2(vb.x * acp[2] - ad.x, vb.y * acp[3] - ad.y);
            } else {
                *(float2*)&Out[r0 * DIMN + col] =
                    make_float2(acp[0] + ad.x, acp[1] + ad.y);
                *(float2*)&Out[(r0 + 8) * DIMN + col] =
                    make_float2(acp[2] + ad.x, acp[3] + ad.y);
            }
        }
    }
}

// ---------------------------------------------------------------------------
// Launch. Inputs: v1, v2, block_W, block_b, row_weights, lin_W, lin_b
// ---------------------------------------------------------------------------
extern "C" void kernel_launch(void* const* d_in, const int* in_sizes, int n_in,
                              void* d_out, int out_size) {
    const float* v1   = (const float*)d_in[0];
    const float* v2   = (const float*)d_in[1];
    const float* bW   = (const float*)d_in[2];
    const float* bB   = (const float*)d_in[3];
    const float* rw   = (const float*)d_in[4];
    const float* linW = (const float*)d_in[5];
    const float* linb = (const float*)d_in[6];
    float* out = (float*)d_out;

    const int nblocks = in_sizes[2] / (DIMN * DIMN);
    const int batch   = in_sizes[0] / DIMN;

    float* gPt;  cudaGetSymbolAddress((void**)&gPt, g_Pt);
    float* gT;   cudaGetSymbolAddress((void**)&gT, g_t);
    float* gcb;  cudaGetSymbolAddress((void**)&gcb, g_cbar);

    cudaFuncSetAttribute(mma_gemm<0>, cudaFuncAttributeMaxDynamicSharedMemorySize, SMEM_BYTES);
    cudaFuncSetAttribute(mma_gemm<1>, cudaFuncAttributeMaxDynamicSharedMemorySize, SMEM_BYTES);

    zero_kernel<<<1, DIMN>>>();
    prep_kernel<<<(DIMN * DIMN + 255) / 256, 256>>>(bW, bB, rw, nblocks);

    dim3 grid(DIMN / BN, batch / BM);
    mma_gemm<0><<<grid, 128, SMEM_BYTES>>>(v1, gPt, rw, v2, gcb, gT);
    mma_gemm<1><<<grid, 128, SMEM_BYTES>>>(gT, linW, nullptr, nullptr, linb, out);
}

// round 4
// speedup vs baseline: 1.6391x; 1.6391x over previous
#include <cuda_runtime.h>
#include <cstdint>

#define DIMN 384
#define KS_TOT 48          // 384 / 8 k-steps
#define MAXBATCH 1024
#define BM 64
#define BN 64
#define PSTRIDE 196        // uint2 per panel row (48*4=192 + 4 pad) -> conflict-free
#define PANEL_U2 (64 * PSTRIDE)
#define SMEM_BYTES (2 * PANEL_U2 * 8)

// Scratch (no cudaMalloc allowed)
__device__ float g_Pt[DIMN * DIMN];     // transposed prod_k(1-W_k):  Pt[j][i] = P[i][j]
__device__ float g_cbar[DIMN];          // sum_i r[i] * C[i,j]
__device__ float g_t[MAXBATCH * DIMN];  // pooled intermediate

__device__ __forceinline__ uint32_t f2tf32(float x) {
    uint32_t y;
    asm("cvt.rna.tf32.f32 %0, %1;" : "=r"(y) : "f"(x));
    return y;
}

__device__ __forceinline__ void mma8(float* d, const uint32_t* a, const uint32_t* b) {
    asm("mma.sync.aligned.m16n8k8.row.col.f32.tf32.tf32.f32 "
        "{%0,%1,%2,%3}, {%4,%5,%6,%7}, {%8,%9}, {%0,%1,%2,%3};"
        : "+f"(d[0]), "+f"(d[1]), "+f"(d[2]), "+f"(d[3])
        : "r"(a[0]), "r"(a[1]), "r"(a[2]), "r"(a[3]),
          "r"(b[0]), "r"(b[1]));
}

// ---------------------------------------------------------------------------
__global__ void zero_kernel() {
    g_cbar[threadIdx.x] = 0.f;
}

// prep: Pt[j][i] = prod_k(1-W_k)[i][j];  cbar[j] += r[i]*C[i][j] via RED.
__global__ void prep_kernel(const float* __restrict__ W,
                            const float* __restrict__ Bb,
                            const float* __restrict__ rw,
                            int nblocks) {
    int idx = blockIdx.x * blockDim.x + threadIdx.x;
    if (idx >= DIMN * DIMN) return;
    float p = 1.0f, c = 0.0f;
    for (int k = 0; k < nblocks; k++) {
        float om = 1.0f - W[k * DIMN * DIMN + idx];
        float b  = Bb[k * DIMN * DIMN + idx];
        p *= om;
        c = c * om + b;
    }
    int i = idx / DIMN, j = idx - i * DIMN;
    g_Pt[j * DIMN + i] = p;
    atomicAdd(&g_cbar[j], rw[i] * c);
}

// ---------------------------------------------------------------------------
// Full-K-panel tf32 GEMM. 64x64 tile / CTA, 8 warps (16x32 warp tiles),
// single __syncthreads, fully-unrolled immediate-offset mainloop.
// MODE 0: t   = v2 .* ((rw.*v1) @ P)   - cbar   (Asrc=v1,  Bsrc=g_Pt [n][k])
// MODE 1: out = (g_t @ linW^T)         + linb   (Asrc=g_t, Bsrc=linW [n][k])
// ---------------------------------------------------------------------------
template <int MODE>
__global__ __launch_bounds__(256, 1)
void mma_gemm(const float* __restrict__ Asrc,
              const float* __restrict__ Bsrc,
              const float* __restrict__ rw,
              const float* __restrict__ v2,
              const float* __restrict__ addv,
              float* __restrict__ Out) {
    extern __shared__ __align__(16) uint2 sm[];
    uint2* Ap = sm;
    uint2* Bp = sm + PANEL_U2;

    const int tid  = threadIdx.x;
    const int lane = tid & 31;
    const int wid  = tid >> 5;
    const int g    = lane >> 2;
    const int t4   = lane & 3;
    const int wm   = wid & 3;    // 4 row groups of 16
    const int wn   = wid >> 2;   // 2 col halves of 32
    const int m0   = blockIdx.y * BM;
    const int n0   = blockIdx.x * BN;

    // ---- load A panel: 3072 tasks / 256 threads = 12 iters ----
#pragma unroll
    for (int it = 0; it < 12; it++) {
        int task = tid + it * 256;
        int m = task / KS_TOT, ks = task - m * KS_TOT;
        const float* src = &Asrc[(m0 + m) * DIMN + ks * 8];
        float4 lo = *(const float4*)src;
        float4 hi = *(const float4*)(src + 4);
        if (MODE == 0) {
            float4 wl = *(const float4*)&rw[ks * 8];
            float4 wh = *(const float4*)&rw[ks * 8 + 4];
            lo.x *= wl.x; lo.y *= wl.y; lo.z *= wl.z; lo.w *= wl.w;
            hi.x *= wh.x; hi.y *= wh.y; hi.z *= wh.z; hi.w *= wh.w;
        }
        uint4* dst = (uint4*)&Ap[m * PSTRIDE + ks * 4];
        dst[0] = make_uint4(f2tf32(lo.x), f2tf32(hi.x), f2tf32(lo.y), f2tf32(hi.y));
        dst[1] = make_uint4(f2tf32(lo.z), f2tf32(hi.z), f2tf32(lo.w), f2tf32(hi.w));
    }
    // ---- load B panel (Bsrc is [n][k] row-major for both modes) ----
#pragma unroll
    for (int it = 0; it < 12; it++) {
        int task = tid + it * 256;
        int n = task / KS_TOT, ks = task - n * KS_TOT;
        const float* src = &Bsrc[(n0 + n) * DIMN + ks * 8];
        float4 lo = *(const float4*)src;
        float4 hi = *(const float4*)(src + 4);
        uint4* dst = (uint4*)&Bp[n * PSTRIDE + ks * 4];
        dst[0] = make_uint4(f2tf32(lo.x), f2tf32(hi.x), f2tf32(lo.y), f2tf32(hi.y));
        dst[1] = make_uint4(f2tf32(lo.z), f2tf32(hi.z), f2tf32(lo.w), f2tf32(hi.w));
    }
    __syncthreads();

    // ---- compute: 48 unrolled ks-steps, immediate smem offsets ----
    float acc[4][4];
#pragma unroll
    for (int nf = 0; nf < 4; nf++)
#pragma unroll
        for (int c = 0; c < 4; c++) acc[nf][c] = 0.f;

    const uint2* aLo = &Ap[(wm * 16 + g) * PSTRIDE + t4];      // rows r, r+8
    const uint2* aHi = aLo + 8 * PSTRIDE;
    const uint2* b0  = &Bp[(wn * 32 + g) * PSTRIDE + t4];      // + nf*8*PSTRIDE

#pragma unroll
    for (int ks = 0; ks < KS_TOT; ks++) {
        const int off = ks * 4;                                 // immediate after unroll
        uint2 lo = aLo[off];
        uint2 hi = aHi[off];
        uint32_t a[4] = {lo.x, hi.x, lo.y, hi.y};
#pragma unroll
        for (int nf = 0; nf < 4; nf++) {
            uint2 u = b0[nf * 8 * PSTRIDE + off];
            uint32_t b[2] = {u.x, u.y};
            mma8(acc[nf], a, b);
        }
    }

    // ---- epilogue ----
    const int r0 = m0 + wm * 16 + g;
#pragma unroll
    for (int nf = 0; nf < 4; nf++) {
        const int col = n0 + wn * 32 + nf * 8 + 2 * t4;
        float2 ad = *(const float2*)&addv[col];
        float* acp = acc[nf];
        if (MODE == 0) {
            float2 va = *(const float2*)&v2[r0 * DIMN + col];
            float2 vb = *(const float2*)&v2[(r0 + 8) * DIMN + col];
            *(float2*)&Out[r0 * DIMN + col] =
                make_float2(va.x * acp[0] - ad.x, va.y * acp[1] - ad.y);
            *(float2*)&Out[(r0 + 8) * DIMN + col] =
                make_float2(vb.x * acp[2] - ad.x, vb.y * acp[3] - ad.y);
        } else {
            *(float2*)&Out[r0 * DIMN + col] =
                make_float2(acp[0] + ad.x, acp[1] + ad.y);
            *(float2*)&Out[(r0 + 8) * DIMN + col] =
                make_float2(acp[2] + ad.x, acp[3] + ad.y);
        }
    }
}

// ---------------------------------------------------------------------------
// Launch. Inputs: v1, v2, block_W, block_b, row_weights, lin_W, lin_b
// ---------------------------------------------------------------------------
extern "C" void kernel_launch(void* const* d_in, const int* in_sizes, int n_in,
                              void* d_out, int out_size) {
    const float* v1   = (const float*)d_in[0];
    const float* v2   = (const float*)d_in[1];
    const float* bW   = (const float*)d_in[2];
    const float* bB   = (const float*)d_in[3];
    const float* rw   = (const float*)d_in[4];
    const float* linW = (const float*)d_in[5];
    const float* linb = (const float*)d_in[6];
    float* out = (float*)d_out;

    const int nblocks = in_sizes[2] / (DIMN * DIMN);
    const int batch   = in_sizes[0] / DIMN;

    float* gPt;  cudaGetSymbolAddress((void**)&gPt, g_Pt);
    float* gT;   cudaGetSymbolAddress((void**)&gT, g_t);
    float* gcb;  cudaGetSymbolAddress((void**)&gcb, g_cbar);

    cudaFuncSetAttribute(mma_gemm<0>, cudaFuncAttributeMaxDynamicSharedMemorySize, SMEM_BYTES);
    cudaFuncSetAttribute(mma_gemm<1>, cudaFuncAttributeMaxDynamicSharedMemorySize, SMEM_BYTES);

    zero_kernel<<<1, DIMN>>>();
    prep_kernel<<<(DIMN * DIMN + 255) / 256, 256>>>(bW, bB, rw, nblocks);

    dim3 grid(DIMN / BN, batch / BM);
    mma_gemm<0><<<grid, 256, SMEM_BYTES>>>(v1, gPt, rw, v2, gcb, gT);
    mma_gemm<1><<<grid, 256, SMEM_BYTES>>>(gT, linW, nullptr, nullptr, linb, out);
}

// round 6
// speedup vs baseline: 1.8803x; 1.1472x over previous
#include <cuda_runtime.h>
#include <cstdint>

#define DIMN 384
#define NP 192              // packed uint2 per row (384 tf32 values, paired {k, k+4})
#define PS 196              // smem row pitch in uint2 (4 pad -> conflict-free frags)
#define BM 32
#define BN 32
#define KS_TOT 48
#define SMEM_GEMM (2 * 32 * PS * 8)   // 100352 B -> 2 CTAs/SM

// Scratch (no cudaMalloc allowed)
__device__ __align__(16) uint2 g_v1p[1024 * NP];   // packed tf32 v1
__device__ __align__(16) uint2 g_lwp[DIMN * NP];   // packed tf32 lin_W
__device__ __align__(16) uint2 g_Ptp[DIMN * NP];   // packed tf32 rw[i]*P[i][j], row j
__device__ __align__(16) uint2 g_tp[1024 * NP];    // packed tf32 t (gemm0 out)
__device__ float g_cbar[DIMN];

__device__ __forceinline__ uint32_t f2tf32(float x) {
    uint32_t y; asm("cvt.rna.tf32.f32 %0, %1;" : "=r"(y) : "f"(x)); return y;
}
__device__ __forceinline__ uint32_t smem_u32(const void* p) {
    uint32_t a;
    asm("{ .reg .u64 t; cvta.to.shared.u64 t, %1; cvt.u32.u64 %0, t; }" : "=r"(a) : "l"(p));
    return a;
}
__device__ __forceinline__ void cp16(uint32_t dst, const void* src) {
    asm volatile("cp.async.cg.shared.global [%0], [%1], 16;" :: "r"(dst), "l"(src) : "memory");
}
__device__ __forceinline__ void cp_wait_all() {
    asm volatile("cp.async.commit_group;" ::: "memory");
    asm volatile("cp.async.wait_group 0;" ::: "memory");
}
__device__ __forceinline__ void mma8(float* d, const uint32_t* a, uint32_t b0, uint32_t b1) {
    asm("mma.sync.aligned.m16n8k8.row.col.f32.tf32.tf32.f32 "
        "{%0,%1,%2,%3}, {%4,%5,%6,%7}, {%8,%9}, {%0,%1,%2,%3};"
        : "+f"(d[0]), "+f"(d[1]), "+f"(d[2]), "+f"(d[3])
        : "r"(a[0]), "r"(a[1]), "r"(a[2]), "r"(a[3]), "r"(b0), "r"(b1));
}

// ---------------------------------------------------------------------------
// cvt_pack: pack v1 (1024 rows) and lin_W (384 rows) to paired tf32.
// Pair slot s = ks*4+t4 holds {src[8ks+t4], src[8ks+t4+4]}.
// Block 0 also zeroes g_cbar (prep's atomics run in a later kernel).
// ---------------------------------------------------------------------------
__global__ __launch_bounds__(192)
void cvt_pack_kernel(const float* __restrict__ v1, const float* __restrict__ linW) {
    const int row = blockIdx.x;
    const int s = threadIdx.x;                 // 0..191
    const int k0 = (s >> 2) * 8 + (s & 3);
    const float* src;
    uint2* dst;
    if (row < 1024) { src = v1 + row * DIMN;          dst = g_v1p + row * NP; }
    else            { src = linW + (row - 1024) * DIMN; dst = g_lwp + (row - 1024) * NP; }
    dst[s] = make_uint2(f2tf32(src[k0]), f2tf32(src[k0 + 4]));
    if (row == 0) { g_cbar[s] = 0.f; g_cbar[s + 192] = 0.f; }
}

// ---------------------------------------------------------------------------
// prep: per 32x32 tile of (i,j): p = prod(1-W_k), c = chain bias.
// Writes g_Ptp[j][pairs over i] = rw[i]*p (transposed+packed via smem),
// and accumulates cbar[j] += sum_i rw[i]*c (smem-reduced, few atomics).
// ---------------------------------------------------------------------------
__global__ __launch_bounds__(256)
void prep_kernel(const float* __restrict__ W, const float* __restrict__ Bb,
                 const float* __restrict__ rw, int nblocks) {
    __shared__ float pt[32][33];
    __shared__ float cp[32][33];
    const int tid = threadIdx.x;
    const int bi = blockIdx.x, bj = blockIdx.y;
    const int il = tid >> 3, j4 = (tid & 7) * 4;
    const int gi = bi * 32 + il;
    const int gj = bj * 32 + j4;

    float4 p = make_float4(1.f, 1.f, 1.f, 1.f);
    float4 c = make_float4(0.f, 0.f, 0.f, 0.f);
    for (int k = 0; k < nblocks; k++) {
        const float* base = &W[(size_t)k * DIMN * DIMN + gi * DIMN + gj];
        const float* bb   = &Bb[(size_t)k * DIMN * DIMN + gi * DIMN + gj];
        float4 w = *(const float4*)base;
        float4 b = *(const float4*)bb;
        float4 om = make_float4(1.f - w.x, 1.f - w.y, 1.f - w.z, 1.f - w.w);
        p.x *= om.x; p.y *= om.y; p.z *= om.z; p.w *= om.w;
        c.x = c.x * om.x + b.x; c.y = c.y * om.y + b.y;
        c.z = c.z * om.z + b.z; c.w = c.w * om.w + b.w;
    }
    const float ri = rw[gi];
    pt[il][j4] = ri * p.x; pt[il][j4 + 1] = ri * p.y;
    pt[il][j4 + 2] = ri * p.z; pt[il][j4 + 3] = ri * p.w;
    cp[il][j4] = ri * c.x; cp[il][j4 + 1] = ri * c.y;
    cp[il][j4 + 2] = ri * c.z; cp[il][j4 + 3] = ri * c.w;
    __syncthreads();

    if (tid < 32) {
        float s = 0.f;
#pragma unroll
        for (int i = 0; i < 32; i++) s += cp[i][tid];
        atomicAdd(&g_cbar[bj * 32 + tid], s);
    }
    // transposed pack: row j gets pairs over i
#pragma unroll
    for (int q = tid; q < 512; q += 256) {
        int j = q >> 4, s = q & 15;
        int i0 = (s >> 2) * 8 + (s & 3);
        g_Ptp[(bj * 32 + j) * NP + bi * 16 + s] =
            make_uint2(f2tf32(pt[i0][j]), f2tf32(pt[i0 + 4][j]));
    }
}

// ---------------------------------------------------------------------------
// Full-K tf32 mma.sync GEMM, 32x32 tile / CTA, 128 thr, 4 warps of 16x16.
// Operands pre-packed -> cp.async straight copy into smem (pitch PS).
// MODE 0: t = v2 .* (v1 @ (rw*P)) - cbar, written PACKED to g_tp
// MODE 1: out = (t @ linW^T) + linb, written f32 to d_out
// ---------------------------------------------------------------------------
template <int MODE>
__global__ __launch_bounds__(128)
void mma_gemm(const uint2* __restrict__ Ap, const uint2* __restrict__ Bp,
              const float* __restrict__ v2, const float* __restrict__ cbar,
              const float* __restrict__ linb, void* __restrict__ OutV) {
    extern __shared__ __align__(16) uint2 sm[];
    uint2* Asm = sm;                 // 32 rows x PS
    uint2* Bsm = sm + 32 * PS;

    const int tid = threadIdx.x;
    const int lane = tid & 31, wid = tid >> 5;
    const int g = lane >> 2, t4 = lane & 3;
    const int wm = wid & 1, wn = wid >> 1;
    const int m0 = blockIdx.y * BM, n0 = blockIdx.x * BN;

    // ---- cp.async load: thread t handles row t>>2, chunks (t&3)+4j ----
    {
        const int row = tid >> 2, c0 = tid & 3;
        const uint32_t aBase = smem_u32(Asm) + row * (PS * 8);
        const uint32_t bBase = smem_u32(Bsm) + row * (PS * 8);
        const char* aSrc = (const char*)(Ap + (size_t)(m0 + row) * NP);
        const char* bSrc = (const char*)(Bp + (size_t)(n0 + row) * NP);
#pragma unroll
        for (int j = 0; j < 24; j++) {
            int off = (c0 + 4 * j) * 16;
            cp16(aBase + off, aSrc + off);
            cp16(bBase + off, bSrc + off);
        }
    }
    cp_wait_all();
    __syncthreads();

    // ---- mainloop: 48 ks-steps, 4 LDS.64 + 2 MMA each, no barriers ----
    float acc[2][4] = {};
    const uint2* aB = &Asm[(wm * 16 + g) * PS + t4];
    const uint2* bB = &Bsm[(wn * 16 + g) * PS + t4];
#pragma unroll
    for (int ks = 0; ks < KS_TOT; ks++) {
        uint2 alo = aB[ks * 4];
        uint2 ahi = aB[8 * PS + ks * 4];
        uint32_t a[4] = {alo.x, ahi.x, alo.y, ahi.y};
        uint2 b0 = bB[ks * 4];
        uint2 b1 = bB[8 * PS + ks * 4];
        mma8(acc[0], a, b0.x, b0.y);
        mma8(acc[1], a, b1.x, b1.y);
    }

    // ---- epilogue ----
    const int r0 = m0 + wm * 16 + g, r1 = r0 + 8;
#pragma unroll
    for (int nf = 0; nf < 2; nf++) {
        const int cl = wn * 16 + nf * 8 + 2 * t4;
        const int C = n0 + cl;
        if (MODE == 0) {
            float2 cb = *(const float2*)&cbar[C];
            float2 va = *(const float2*)&v2[r0 * DIMN + C];
            float2 vb = *(const float2*)&v2[r1 * DIMN + C];
            float tv00 = va.x * acc[nf][0] - cb.x;
            float tv01 = va.y * acc[nf][1] - cb.y;
            float tv10 = vb.x * acc[nf][2] - cb.x;
            float tv11 = vb.y * acc[nf][3] - cb.y;
            // pair with col C+4 (held by lane+2)
            float u00 = __shfl_down_sync(0xffffffffu, tv00, 2);
            float u01 = __shfl_down_sync(0xffffffffu, tv01, 2);
            float u10 = __shfl_down_sync(0xffffffffu, tv10, 2);
            float u11 = __shfl_down_sync(0xffffffffu, tv11, 2);
            if (t4 < 2) {
                int s0 = (C >> 3) * 4 + 2 * t4;
                *(uint4*)&g_tp[r0 * NP + s0] =
                    make_uint4(f2tf32(tv00), f2tf32(u00), f2tf32(tv01), f2tf32(u01));
                *(uint4*)&g_tp[r1 * NP + s0] =
                    make_uint4(f2tf32(tv10), f2tf32(u10), f2tf32(tv11), f2tf32(u11));
            }
        } else {
            float* Out = (float*)OutV;
            float2 lb = *(const float2*)&linb[C];
            *(float2*)&Out[r0 * DIMN + C] =
                make_float2(acc[nf][0] + lb.x, acc[nf][1] + lb.y);
            *(float2*)&Out[r1 * DIMN + C] =
                make_float2(acc[nf][2] + lb.x, acc[nf][3] + lb.y);
        }
    }
}

// ---------------------------------------------------------------------------
// Launch. Inputs: v1, v2, block_W, block_b, row_weights, lin_W, lin_b
// ---------------------------------------------------------------------------
extern "C" void kernel_launch(void* const* d_in, const int* in_sizes, int n_in,
                              void* d_out, int out_size) {
    const float* v1   = (const float*)d_in[0];
    const float* v2   = (const float*)d_in[1];
    const float* bW   = (const float*)d_in[2];
    const float* bB   = (const float*)d_in[3];
    const float* rw   = (const float*)d_in[4];
    const float* linW = (const float*)d_in[5];
    const float* linb = (const float*)d_in[6];

    const int nblocks = in_sizes[2] / (DIMN * DIMN);
    const int batch   = in_sizes[0] / DIMN;

    uint2 *gv1p, *glwp, *gPtp, *gtp; float* gcb;
    cudaGetSymbolAddress((void**)&gv1p, g_v1p);
    cudaGetSymbolAddress((void**)&glwp, g_lwp);
    cudaGetSymbolAddress((void**)&gPtp, g_Ptp);
    cudaGetSymbolAddress((void**)&gtp,  g_tp);
    cudaGetSymbolAddress((void**)&gcb,  g_cbar);

    cudaFuncSetAttribute(mma_gemm<0>, cudaFuncAttributeMaxDynamicSharedMemorySize, SMEM_GEMM);
    cudaFuncSetAttribute(mma_gemm<1>, cudaFuncAttributeMaxDynamicSharedMemorySize, SMEM_GEMM);

    // 1) pack v1 + linW to tf32 pairs, zero cbar
    cvt_pack_kernel<<<batch + DIMN, 192>>>(v1, linW);
    // 2) P/C chain, transposed+packed Pt (rw folded), cbar reduction
    prep_kernel<<<dim3(12, 12), 256>>>(bW, bB, rw, nblocks);
    // 3) t = v2.*(v1 @ rwP) - cbar   (packed out)
    dim3 grid(DIMN / BN, batch / BM);   // (12, 32) = 384 CTAs
    mma_gemm<0><<<grid, 128, SMEM_GEMM>>>(gv1p, gPtp, v2, gcb, nullptr, nullptr);
    // 4) out = t @ linW^T + linb
    mma_gemm<1><<<grid, 128, SMEM_GEMM>>>(gtp, glwp, nullptr, nullptr, linb, d_out);
}

// round 8
// speedup vs baseline: 1.8986x; 1.0097x over previous
#include <cuda_runtime.h>
#include <cstdint>

#define DIMN 384
#define NP 192              // packed uint2 per row (384 tf32 values, paired {k, k+4})
#define PS 196              // smem row pitch in uint2 (4 pad -> conflict-free frags)
#define BM 32
#define BN 32
#define SMEM_GEMM (2 * 32 * PS * 8)   // 100352 B -> 2 CTAs/SM

// Scratch (no cudaMalloc allowed)
__device__ __align__(16) uint2 g_v1p[1024 * NP];   // packed tf32 v1
__device__ __align__(16) uint2 g_lwp[DIMN * NP];   // packed tf32 lin_W
__device__ __align__(16) uint2 g_Ptp[DIMN * NP];   // packed tf32 rw[i]*P[i][j], row j
__device__ __align__(16) uint2 g_tp[1024 * NP];    // packed tf32 t (gemm0 out)
__device__ float g_cbar[DIMN];

__device__ __forceinline__ uint32_t f2tf32(float x) {
    uint32_t y; asm("cvt.rna.tf32.f32 %0, %1;" : "=r"(y) : "f"(x)); return y;
}
__device__ __forceinline__ uint32_t smem_u32(const void* p) {
    uint32_t a;
    asm("{ .reg .u64 t; cvta.to.shared.u64 t, %1; cvt.u32.u64 %0, t; }" : "=r"(a) : "l"(p));
    return a;
}
__device__ __forceinline__ void cp16(uint32_t dst, const void* src) {
    asm volatile("cp.async.cg.shared.global [%0], [%1], 16;" :: "r"(dst), "l"(src) : "memory");
}
__device__ __forceinline__ void cp_wait_all() {
    asm volatile("cp.async.commit_group;" ::: "memory");
    asm volatile("cp.async.wait_group 0;" ::: "memory");
}
__device__ __forceinline__ void mma8(float* d, const uint32_t* a, uint32_t b0, uint32_t b1) {
    asm("mma.sync.aligned.m16n8k8.row.col.f32.tf32.tf32.f32 "
        "{%0,%1,%2,%3}, {%4,%5,%6,%7}, {%8,%9}, {%0,%1,%2,%3};"
        : "+f"(d[0]), "+f"(d[1]), "+f"(d[2]), "+f"(d[3])
        : "r"(a[0]), "r"(a[1]), "r"(a[2]), "r"(a[3]), "r"(b0), "r"(b1));
}

// ---------------------------------------------------------------------------
// cvt_pack: pack v1 (1024 rows) and lin_W (384 rows) to paired tf32.
// Pair slot s = ks*4+t4 holds {src[8ks+t4], src[8ks+t4+4]}.
// Block 0 also zeroes g_cbar.
// ---------------------------------------------------------------------------
__global__ __launch_bounds__(192)
void cvt_pack_kernel(const float* __restrict__ v1, const float* __restrict__ linW) {
    const int row = blockIdx.x;
    const int s = threadIdx.x;                 // 0..191
    const int k0 = (s >> 2) * 8 + (s & 3);
    const float* src;
    uint2* dst;
    if (row < 1024) { src = v1 + row * DIMN;          dst = g_v1p + row * NP; }
    else            { src = linW + (row - 1024) * DIMN; dst = g_lwp + (row - 1024) * NP; }
    dst[s] = make_uint2(f2tf32(src[k0]), f2tf32(src[k0 + 4]));
    if (row == 0) { g_cbar[s] = 0.f; g_cbar[s + 192] = 0.f; }
}

// ---------------------------------------------------------------------------
// prep: per 32x32 tile of (i,j): p = prod(1-W_k), c = chain bias.
// Writes g_Ptp[j][pairs over i] = rw[i]*p (transposed+packed via smem),
// and accumulates cbar[j] += sum_i rw[i]*c.
// ---------------------------------------------------------------------------
__global__ __launch_bounds__(256)
void prep_kernel(const float* __restrict__ W, const float* __restrict__ Bb,
                 const float* __restrict__ rw, int nblocks) {
    __shared__ float pt[32][33];
    __shared__ float cp[32][33];
    const int tid = threadIdx.x;
    const int bi = blockIdx.x, bj = blockIdx.y;
    const int il = tid >> 3, j4 = (tid & 7) * 4;
    const int gi = bi * 32 + il;
    const int gj = bj * 32 + j4;

    float4 p = make_float4(1.f, 1.f, 1.f, 1.f);
    float4 c = make_float4(0.f, 0.f, 0.f, 0.f);
    for (int k = 0; k < nblocks; k++) {
        const float* base = &W[(size_t)k * DIMN * DIMN + gi * DIMN + gj];
        const float* bb   = &Bb[(size_t)k * DIMN * DIMN + gi * DIMN + gj];
        float4 w = *(const float4*)base;
        float4 b = *(const float4*)bb;
        float4 om = make_float4(1.f - w.x, 1.f - w.y, 1.f - w.z, 1.f - w.w);
        p.x *= om.x; p.y *= om.y; p.z *= om.z; p.w *= om.w;
        c.x = c.x * om.x + b.x; c.y = c.y * om.y + b.y;
        c.z = c.z * om.z + b.z; c.w = c.w * om.w + b.w;
    }
    const float ri = rw[gi];
    pt[il][j4] = ri * p.x; pt[il][j4 + 1] = ri * p.y;
    pt[il][j4 + 2] = ri * p.z; pt[il][j4 + 3] = ri * p.w;
    cp[il][j4] = ri * c.x; cp[il][j4 + 1] = ri * c.y;
    cp[il][j4 + 2] = ri * c.z; cp[il][j4 + 3] = ri * c.w;
    __syncthreads();

    if (tid < 32) {
        float s = 0.f;
#pragma unroll
        for (int i = 0; i < 32; i++) s += cp[i][tid];
        atomicAdd(&g_cbar[bj * 32 + tid], s);
    }
#pragma unroll
    for (int q = tid; q < 512; q += 256) {
        int j = q >> 4, s = q & 15;
        int i0 = (s >> 2) * 8 + (s & 3);
        g_Ptp[(bj * 32 + j) * NP + bi * 16 + s] =
            make_uint2(f2tf32(pt[i0][j]), f2tf32(pt[i0 + 4][j]));
    }
}

// ---------------------------------------------------------------------------
// Full-K tf32 mma.sync GEMM, 32x32 tile / CTA, 256 thr / 8 warps.
// Warp (wm, wn, kh): 16x16 sub-tile over K-half kh (24 ks-steps),
// register double-buffered fragments, smem cross-half reduction.
// MODE 0: t = v2 .* (v1 @ (rw*P)) - cbar, written PACKED to g_tp
// MODE 1: out = (t @ linW^T) + linb, written f32 to d_out
// ---------------------------------------------------------------------------
template <int MODE>
__global__ __launch_bounds__(256)
void mma_gemm(const uint2* __restrict__ Ap, const uint2* __restrict__ Bp,
              const float* __restrict__ v2, const float* __restrict__ cbar,
              const float* __restrict__ linb, void* __restrict__ OutV) {
    extern __shared__ __align__(16) uint2 sm[];
    uint2* Asm = sm;                 // 32 rows x PS
    uint2* Bsm = sm + 32 * PS;

    const int tid = threadIdx.x;
    const int lane = tid & 31, wid = tid >> 5;
    const int g = lane >> 2, t4 = lane & 3;
    const int wm = wid & 1, wn = (wid >> 1) & 1, kh = wid >> 2;
    const int m0 = blockIdx.y * BM, n0 = blockIdx.x * BN;

    // ---- cp.async: tid<128 -> A panel, tid>=128 -> B panel.
    // 4 threads/row, each 24 chunks of 16B -> full 1536B row. ----
    {
        const int row = (tid & 127) >> 2, c0 = tid & 3;
        const bool isB = tid >= 128;
        const uint32_t sBase = smem_u32(isB ? Bsm : Asm) + row * (PS * 8);
        const char* src = (const char*)((isB ? Bp + (size_t)(n0 + row) * NP
                                             : Ap + (size_t)(m0 + row) * NP));
#pragma unroll
        for (int j = 0; j < 24; j++) {
            int off = (c0 + 4 * j) * 16;
            cp16(sBase + off, src + off);
        }
    }
    cp_wait_all();
    __syncthreads();

    // ---- mainloop: 24 ks-steps on this K-half, register double-buffered ----
    float acc[2][4] = {};
    const uint2* aB = &Asm[(wm * 16 + g) * PS + t4] + kh * 96;
    const uint2* bB = &Bsm[(wn * 16 + g) * PS + t4] + kh * 96;

    uint2 alo[2], ahi[2], bf0[2], bf1[2];
    alo[0] = aB[0]; ahi[0] = aB[8 * PS];
    bf0[0] = bB[0]; bf1[0] = bB[8 * PS];
#pragma unroll
    for (int ks = 0; ks < 24; ks++) {
        const int cur = ks & 1, nxt = cur ^ 1;
        if (ks < 23) {
            const int off = (ks + 1) * 4;
            alo[nxt] = aB[off]; ahi[nxt] = aB[8 * PS + off];
            bf0[nxt] = bB[off]; bf1[nxt] = bB[8 * PS + off];
        }
        uint32_t a[4] = {alo[cur].x, ahi[cur].x, alo[cur].y, ahi[cur].y};
        mma8(acc[0], a, bf0[cur].x, bf0[cur].y);
        mma8(acc[1], a, bf1[cur].x, bf1[cur].y);
    }

    // ---- cross-half reduction through smem (reuse panel space) ----
    float* red = (float*)sm;         // 32 x 34 floats = 4352 B
    __syncthreads();                 // all panel reads done
    if (kh == 1) {
        const int r0l = wm * 16 + g;
#pragma unroll
        for (int nf = 0; nf < 2; nf++) {
            const int c = wn * 16 + nf * 8 + 2 * t4;
            *(float2*)&red[r0l * 34 + c]       = make_float2(acc[nf][0], acc[nf][1]);
            *(float2*)&red[(r0l + 8) * 34 + c] = make_float2(acc[nf][2], acc[nf][3]);
        }
    }
    __syncthreads();
    if (kh == 1) return;

    const int r0l = wm * 16 + g;
#pragma unroll
    for (int nf = 0; nf < 2; nf++) {
        const int c = wn * 16 + nf * 8 + 2 * t4;
        float2 p0 = *(const float2*)&red[r0l * 34 + c];
        float2 p1 = *(const float2*)&red[(r0l + 8) * 34 + c];
        acc[nf][0] += p0.x; acc[nf][1] += p0.y;
        acc[nf][2] += p1.x; acc[nf][3] += p1.y;
    }

    // ---- epilogue (kh==0 warps only) ----
    const int r0 = m0 + r0l, r1 = r0 + 8;
#pragma unroll
    for (int nf = 0; nf < 2; nf++) {
        const int C = n0 + wn * 16 + nf * 8 + 2 * t4;
        if (MODE == 0) {
            float2 cb = *(const float2*)&cbar[C];
            float2 va = *(const float2*)&v2[r0 * DIMN + C];
            float2 vb = *(const float2*)&v2[r1 * DIMN + C];
            float tv00 = va.x * acc[nf][0] - cb.x;
            float tv01 = va.y * acc[nf][1] - cb.y;
            float tv10 = vb.x * acc[nf][2] - cb.x;
            float tv11 = vb.y * acc[nf][3] - cb.y;
            float u00 = __shfl_down_sync(0xffffffffu, tv00, 2);
            float u01 = __shfl_down_sync(0xffffffffu, tv01, 2);
            float u10 = __shfl_down_sync(0xffffffffu, tv10, 2);
            float u11 = __shfl_down_sync(0xffffffffu, tv11, 2);
            if (t4 < 2) {
                int s0 = (C >> 3) * 4 + 2 * t4;
                *(uint4*)&g_tp[r0 * NP + s0] =
                    make_uint4(f2tf32(tv00), f2tf32(u00), f2tf32(tv01), f2tf32(u01));
                *(uint4*)&g_tp[r1 * NP + s0] =
                    make_uint4(f2tf32(tv10), f2tf32(u10), f2tf32(tv11), f2tf32(u11));
            }
        } else {
            float* Out = (float*)OutV;
            float2 lb = *(const float2*)&linb[C];
            *(float2*)&Out[r0 * DIMN + C] =
                make_float2(acc[nf][0] + lb.x, acc[nf][1] + lb.y);
            *(float2*)&Out[r1 * DIMN + C] =
                make_float2(acc[nf][2] + lb.x, acc[nf][3] + lb.y);
        }
    }
}

// ---------------------------------------------------------------------------
// Launch. Inputs: v1, v2, block_W, block_b, row_weights, lin_W, lin_b
// ---------------------------------------------------------------------------
extern "C" void kernel_launch(void* const* d_in, const int* in_sizes, int n_in,
                              void* d_out, int out_size) {
    const float* v1   = (const float*)d_in[0];
    const float* v2   = (const float*)d_in[1];
    const float* bW   = (const float*)d_in[2];
    const float* bB   = (const float*)d_in[3];
    const float* rw   = (const float*)d_in[4];
    const float* linW = (const float*)d_in[5];
    const float* linb = (const float*)d_in[6];

    const int nblocks = in_sizes[2] / (DIMN * DIMN);
    const int batch   = in_sizes[0] / DIMN;

    uint2 *gv1p, *glwp, *gPtp, *gtp; float* gcb;
    cudaGetSymbolAddress((void**)&gv1p, g_v1p);
    cudaGetSymbolAddress((void**)&glwp, g_lwp);
    cudaGetSymbolAddress((void**)&gPtp, g_Ptp);
    cudaGetSymbolAddress((void**)&gtp,  g_tp);
    cudaGetSymbolAddress((void**)&gcb,  g_cbar);

    cudaFuncSetAttribute(mma_gemm<0>, cudaFuncAttributeMaxDynamicSharedMemorySize, SMEM_GEMM);
    cudaFuncSetAttribute(mma_gemm<1>, cudaFuncAttributeMaxDynamicSharedMemorySize, SMEM_GEMM);

    cvt_pack_kernel<<<batch + DIMN, 192>>>(v1, linW);
    prep_kernel<<<dim3(12, 12), 256>>>(bW, bB, rw, nblocks);
    dim3 grid(DIMN / BN, batch / BM);   // (12, 32) = 384 CTAs
    mma_gemm<0><<<grid, 256, SMEM_GEMM>>>(gv1p, gPtp, v2, gcb, nullptr, nullptr);
    mma_gemm<1><<<grid, 256, SMEM_GEMM>>>(gtp, glwp, nullptr, nullptr, linb, d_out);
}

// round 9
// speedup vs baseline: 2.0838x; 1.0976x over previous
#include <cuda_runtime.h>
#include <cstdint>

#define DIMN 384
#define NP 192                    // uint2 per packed row
#define PS 196                    // B smem pitch in uint2 (conflict-free)
#define A4_CNT 3072               // uint4 per 32-row A block: 48 ks * 16 p * 4 t4
#define SMEM_A4 (A4_CNT * 16)     // 49152 B
#define SMEM_B  (32 * PS * 8)     // 50176 B
#define SMEM_GEMM (SMEM_A4 + SMEM_B)   // 99328 -> 2 CTAs/SM

// Scratch (no cudaMalloc allowed)
// A operands: interleaved uint4 layout [rowblock][ks][p][t4]:
//   p = pairIdx (0..15): rows (32rb + (p&7) + (p>>3)*16, +8)
//   uint4 = {A[r][8ks+t4], A[r][8ks+t4+4], A[r+8][8ks+t4], A[r+8][8ks+t4+4]}
__device__ __align__(16) uint4 g_v1p4[32 * A4_CNT];   // packed v1
__device__ __align__(16) uint4 g_tp4[32 * A4_CNT];    // packed t (gemm0 out)
// B operands: pair layout [n][s]: uint2 = {B[n][8(s>>2)+(s&3)], ... +4}
__device__ __align__(16) uint2 g_lwp[DIMN * NP];      // packed lin_W
__device__ __align__(16) uint2 g_Ptp[DIMN * NP];      // packed rw[i]*P[i][j], row j
__device__ float g_cbar[DIMN];

__device__ __forceinline__ uint32_t f2tf32(float x) {
    uint32_t y; asm("cvt.rna.tf32.f32 %0, %1;" : "=r"(y) : "f"(x)); return y;
}
__device__ __forceinline__ uint32_t smem_u32(const void* p) {
    uint32_t a;
    asm("{ .reg .u64 t; cvta.to.shared.u64 t, %1; cvt.u32.u64 %0, t; }" : "=r"(a) : "l"(p));
    return a;
}
__device__ __forceinline__ void cp16(uint32_t dst, const void* src) {
    asm volatile("cp.async.cg.shared.global [%0], [%1], 16;" :: "r"(dst), "l"(src) : "memory");
}
__device__ __forceinline__ void cp_wait_all() {
    asm volatile("cp.async.commit_group;" ::: "memory");
    asm volatile("cp.async.wait_group 0;" ::: "memory");
}
__device__ __forceinline__ void mma8(float* d, const uint32_t* a, uint32_t b0, uint32_t b1) {
    asm("mma.sync.aligned.m16n8k8.row.col.f32.tf32.tf32.f32 "
        "{%0,%1,%2,%3}, {%4,%5,%6,%7}, {%8,%9}, {%0,%1,%2,%3};"
        : "+f"(d[0]), "+f"(d[1]), "+f"(d[2]), "+f"(d[3])
        : "r"(a[0]), "r"(a[1]), "r"(a[2]), "r"(a[3]), "r"(b0), "r"(b1));
}

// ---------------------------------------------------------------------------
// cvt_pack: blocks [0,384): v1 -> g_v1p4 (interleaved uint4).
//           blocks [384,672): lin_W -> g_lwp (uint2 pairs). Zeroes cbar.
// ---------------------------------------------------------------------------
__global__ __launch_bounds__(256)
void cvt_pack_kernel(const float* __restrict__ v1, const float* __restrict__ linW) {
    const int bid = blockIdx.x, tid = threadIdx.x;
    if (bid < 384) {
        const int idx = bid * 256 + tid;           // 0..98303
        const int rb = idx / A4_CNT, rem = idx - rb * A4_CNT;
        const int ks = rem >> 6, p = (rem >> 2) & 15, t4 = rem & 3;
        const int r = rb * 32 + (p & 7) + ((p >> 3) << 4);
        const int k0 = ks * 8 + t4;
        const float* s0 = v1 + r * DIMN + k0;
        const float* s1 = s0 + 8 * DIMN;
        g_v1p4[idx] = make_uint4(f2tf32(s0[0]), f2tf32(s0[4]),
                                 f2tf32(s1[0]), f2tf32(s1[4]));
        if (idx < DIMN) g_cbar[idx] = 0.f;
    } else {
        const int idx = (bid - 384) * 256 + tid;   // 0..73727
        const int row = idx / NP, s = idx - row * NP;
        const int k0 = (s >> 2) * 8 + (s & 3);
        const float* src = linW + row * DIMN + k0;
        g_lwp[idx] = make_uint2(f2tf32(src[0]), f2tf32(src[4]));
    }
}

// ---------------------------------------------------------------------------
// prep: per 32x32 tile: p = prod(1-W_k), c = chain bias.
// g_Ptp[j][pairs over i] = rw[i]*p (transposed+packed); cbar[j] += rw[i]*c.
// ---------------------------------------------------------------------------
__global__ __launch_bounds__(256)
void prep_kernel(const float* __restrict__ W, const float* __restrict__ Bb,
                 const float* __restrict__ rw, int nblocks) {
    __shared__ float pt[32][33];
    __shared__ float cp[32][33];
    const int tid = threadIdx.x;
    const int bi = blockIdx.x, bj = blockIdx.y;
    const int il = tid >> 3, j4 = (tid & 7) * 4;
    const int gi = bi * 32 + il, gj = bj * 32 + j4;

    float4 p = make_float4(1.f, 1.f, 1.f, 1.f);
    float4 c = make_float4(0.f, 0.f, 0.f, 0.f);
    for (int k = 0; k < nblocks; k++) {
        float4 w = *(const float4*)&W[(size_t)k * DIMN * DIMN + gi * DIMN + gj];
        float4 b = *(const float4*)&Bb[(size_t)k * DIMN * DIMN + gi * DIMN + gj];
        float4 om = make_float4(1.f - w.x, 1.f - w.y, 1.f - w.z, 1.f - w.w);
        p.x *= om.x; p.y *= om.y; p.z *= om.z; p.w *= om.w;
        c.x = c.x * om.x + b.x; c.y = c.y * om.y + b.y;
        c.z = c.z * om.z + b.z; c.w = c.w * om.w + b.w;
    }
    const float ri = rw[gi];
    pt[il][j4] = ri * p.x; pt[il][j4 + 1] = ri * p.y;
    pt[il][j4 + 2] = ri * p.z; pt[il][j4 + 3] = ri * p.w;
    cp[il][j4] = ri * c.x; cp[il][j4 + 1] = ri * c.y;
    cp[il][j4 + 2] = ri * c.z; cp[il][j4 + 3] = ri * c.w;
    __syncthreads();

    if (tid < 32) {
        float s = 0.f;
#pragma unroll
        for (int i = 0; i < 32; i++) s += cp[i][tid];
        atomicAdd(&g_cbar[bj * 32 + tid], s);
    }
#pragma unroll
    for (int q = tid; q < 512; q += 256) {
        int j = q >> 4, s = q & 15;
        int i0 = (s >> 2) * 8 + (s & 3);
        g_Ptp[(bj * 32 + j) * NP + bi * 16 + s] =
            make_uint2(f2tf32(pt[i0][j]), f2tf32(pt[i0 + 4][j]));
    }
}

// ---------------------------------------------------------------------------
// tf32 mma.sync GEMM, 32x32 tile / CTA, 256 thr / 8 warps = wn(2) x kh(4).
// Warp tile 32x16 over a K-quarter (12 ks-steps): per step 2 LDS.128 (A) +
// 2 LDS.64 (B) -> 4 MMAs. Cross-quarter reduction in smem.
// MODE 0: t = v2 .* (v1 @ rwP) - cbar   (out: g_tp4, interleaved packed)
// MODE 1: out = (t @ linW^T) + linb     (out: f32 d_out)
// ---------------------------------------------------------------------------
template <int MODE>
__global__ __launch_bounds__(256)
void mma_gemm(const uint4* __restrict__ Ap4, const uint2* __restrict__ Bp,
              const float* __restrict__ v2, const float* __restrict__ cbar,
              const float* __restrict__ linb, void* __restrict__ OutV) {
    extern __shared__ __align__(16) char smc[];
    uint4* A4 = (uint4*)smc;
    uint2* Bs = (uint2*)(smc + SMEM_A4);

    const int tid = threadIdx.x, lane = tid & 31, wid = tid >> 5;
    const int g = lane >> 2, t4 = lane & 3;
    const int wn = wid & 1, kh = wid >> 1;
    const int rb = blockIdx.y;
    const int m0 = rb * 32, n0 = blockIdx.x * 32;

    // ---- loads: A is a pure linear 48KB copy; B rows re-pitched ----
    {
        const uint32_t aB = smem_u32(A4);
        const char* aS = (const char*)(Ap4 + (size_t)rb * A4_CNT);
#pragma unroll
        for (int j = 0; j < 12; j++) {
            int off = (tid + j * 256) * 16;
            cp16(aB + off, aS + off);
        }
        const int row = tid >> 3, c0 = tid & 7;
        const uint32_t bB = smem_u32(Bs) + row * (PS * 8);
        const char* bS = (const char*)(Bp + (size_t)(n0 + row) * NP);
#pragma unroll
        for (int j = 0; j < 12; j++) {
            int off = (c0 + 8 * j) * 16;
            cp16(bB + off, bS + off);
        }
    }
    cp_wait_all();
    __syncthreads();

    // ---- mainloop: 12 ks-steps on this K-quarter, double-buffered ----
    float acc[2][2][4] = {};
    const uint4* aP = &A4[kh * 12 * 64 + g * 4 + t4];            // +32 for mi=1, +64/ks
    const uint2* bP = &Bs[(wn * 16 + g) * PS + kh * 48 + t4];    // +8*PS for nf=1, +4/ks

    uint4 qa[2][2]; uint2 qb[2][2];
    qa[0][0] = aP[0]; qa[0][1] = aP[32];
    qb[0][0] = bP[0]; qb[0][1] = bP[8 * PS];
#pragma unroll
    for (int ks = 0; ks < 12; ks++) {
        const int cur = ks & 1, nxt = cur ^ 1;
        if (ks < 11) {
            const int oa = (ks + 1) * 64, ob = (ks + 1) * 4;
            qa[nxt][0] = aP[oa]; qa[nxt][1] = aP[oa + 32];
            qb[nxt][0] = bP[ob]; qb[nxt][1] = bP[8 * PS + ob];
        }
#pragma unroll
        for (int mi = 0; mi < 2; mi++) {
            uint32_t a[4] = {qa[cur][mi].x, qa[cur][mi].z, qa[cur][mi].y, qa[cur][mi].w};
            mma8(acc[mi][0], a, qb[cur][0].x, qb[cur][0].y);
            mma8(acc[mi][1], a, qb[cur][1].x, qb[cur][1].y);
        }
    }

    // ---- cross-quarter reduction via smem (reuse A panel region) ----
    float* red = (float*)smc;        // 3 buffers of 32x34 floats (13.3KB)
    __syncthreads();
    if (kh > 0) {
        float* r = red + (kh - 1) * (32 * 34);
#pragma unroll
        for (int mi = 0; mi < 2; mi++) {
            const int rl = mi * 16 + g;
#pragma unroll
            for (int nf = 0; nf < 2; nf++) {
                const int c = wn * 16 + nf * 8 + 2 * t4;
                *(float2*)&r[rl * 34 + c]       = make_float2(acc[mi][nf][0], acc[mi][nf][1]);
                *(float2*)&r[(rl + 8) * 34 + c] = make_float2(acc[mi][nf][2], acc[mi][nf][3]);
            }
        }
    }
    __syncthreads();
    if (kh > 0) return;

#pragma unroll
    for (int b = 0; b < 3; b++) {
        const float* r = red + b * (32 * 34);
#pragma unroll
        for (int mi = 0; mi < 2; mi++) {
            const int rl = mi * 16 + g;
#pragma unroll
            for (int nf = 0; nf < 2; nf++) {
                const int c = wn * 16 + nf * 8 + 2 * t4;
                float2 p0 = *(const float2*)&r[rl * 34 + c];
                float2 p1 = *(const float2*)&r[(rl + 8) * 34 + c];
                acc[mi][nf][0] += p0.x; acc[mi][nf][1] += p0.y;
                acc[mi][nf][2] += p1.x; acc[mi][nf][3] += p1.y;
            }
        }
    }

    // ---- epilogue (kh==0 warps: wn 0,1 cover all 32 cols) ----
#pragma unroll
    for (int mi = 0; mi < 2; mi++) {
        const int r0 = m0 + mi * 16 + g, r1 = r0 + 8;
#pragma unroll
        for (int nf = 0; nf < 2; nf++) {
            const int C = n0 + wn * 16 + nf * 8 + 2 * t4;
            if (MODE == 0) {
                float2 cb = *(const float2*)&cbar[C];
                float2 va = *(const float2*)&v2[r0 * DIMN + C];
                float2 vb = *(const float2*)&v2[r1 * DIMN + C];
                float c0 = va.x * acc[mi][nf][0] - cb.x;
                float c1 = va.y * acc[mi][nf][1] - cb.y;
                float c2 = vb.x * acc[mi][nf][2] - cb.x;
                float c3 = vb.y * acc[mi][nf][3] - cb.y;
                float u0 = __shfl_down_sync(0xffffffffu, c0, 2);
                float u1 = __shfl_down_sync(0xffffffffu, c1, 2);
                float u2 = __shfl_down_sync(0xffffffffu, c2, 2);
                float u3 = __shfl_down_sync(0xffffffffu, c3, 2);
                if (t4 < 2) {
                    const int p = mi * 8 + g;
                    const int ks_g = (n0 + wn * 16 + nf * 8) >> 3;
                    size_t base = (size_t)rb * A4_CNT + ks_g * 64 + p * 4;
                    g_tp4[base + 2 * t4] =
                        make_uint4(f2tf32(c0), f2tf32(u0), f2tf32(c2), f2tf32(u2));
                    g_tp4[base + 2 * t4 + 1] =
                        make_uint4(f2tf32(c1), f2tf32(u1), f2tf32(c3), f2tf32(u3));
                }
            } else {
                float* Out = (float*)OutV;
                float2 lb = *(const float2*)&linb[C];
                *(float2*)&Out[r0 * DIMN + C] =
                    make_float2(acc[mi][nf][0] + lb.x, acc[mi][nf][1] + lb.y);
                *(float2*)&Out[r1 * DIMN + C] =
                    make_float2(acc[mi][nf][2] + lb.x, acc[mi][nf][3] + lb.y);
            }
        }
    }
}

// ---------------------------------------------------------------------------
// Launch. Inputs: v1, v2, block_W, block_b, row_weights, lin_W, lin_b
// ---------------------------------------------------------------------------
extern "C" void kernel_launch(void* const* d_in, const int* in_sizes, int n_in,
                              void* d_out, int out_size) {
    const float* v1   = (const float*)d_in[0];
    const float* v2   = (const float*)d_in[1];
    const float* bW   = (const float*)d_in[2];
    const float* bB   = (const float*)d_in[3];
    const float* rw   = (const float*)d_in[4];
    const float* linW = (const float*)d_in[5];
    const float* linb = (const float*)d_in[6];

    const int nblocks = in_sizes[2] / (DIMN * DIMN);
    const int batch   = in_sizes[0] / DIMN;

    uint4 *gv1p4, *gtp4; uint2 *glwp, *gPtp; float* gcb;
    cudaGetSymbolAddress((void**)&gv1p4, g_v1p4);
    cudaGetSymbolAddress((void**)&gtp4,  g_tp4);
    cudaGetSymbolAddress((void**)&glwp,  g_lwp);
    cudaGetSymbolAddress((void**)&gPtp,  g_Ptp);
    cudaGetSymbolAddress((void**)&gcb,   g_cbar);

    cudaFuncSetAttribute(mma_gemm<0>, cudaFuncAttributeMaxDynamicSharedMemorySize, SMEM_GEMM);
    cudaFuncSetAttribute(mma_gemm<1>, cudaFuncAttributeMaxDynamicSharedMemorySize, SMEM_GEMM);

    cvt_pack_kernel<<<672, 256>>>(v1, linW);
    prep_kernel<<<dim3(12, 12), 256>>>(bW, bB, rw, nblocks);
    dim3 grid(DIMN / 32, batch / 32);   // (12, 32) = 384 CTAs
    mma_gemm<0><<<grid, 256, SMEM_GEMM>>>(gv1p4, gPtp, v2, gcb, nullptr, nullptr);
    mma_gemm<1><<<grid, 256, SMEM_GEMM>>>(gtp4, glwp, nullptr, nullptr, linb, d_out);
}